// round 2
// baseline (speedup 1.0000x reference)
#include <cuda_runtime.h>

#define ZTOT 262144
#define THREADS 128
#define ZT 16   // z per tile (4 warps x 4 z)

__device__ __forceinline__ unsigned long long ffma2(unsigned long long a,
                                                    unsigned long long b,
                                                    unsigned long long c) {
    unsigned long long d;
    asm("fma.rn.f32x2 %0, %1, %2, %3;" : "=l"(d) : "l"(a), "l"(b), "l"(c));
    return d;
}

__device__ __forceinline__ void lds_v2u64(unsigned addr, unsigned long long& a,
                                          unsigned long long& b) {
    asm volatile("ld.shared.v2.u64 {%0,%1}, [%2];" : "=l"(a), "=l"(b) : "r"(addr));
}

__device__ __forceinline__ float2 unpack2(unsigned long long v) {
    float2 r;
    asm("mov.b64 {%0,%1}, %2;" : "=f"(r.x), "=f"(r.y) : "l"(v));
    return r;
}

// smem layout (in floats)
#define OFF_W0   0        // 8192  (w0 * 0.125)
#define OFF_W1   8192     // 8192  (w1 * 0.125)
#define OFF_TPW  16384    // 256   (C-consts folded in)
#define OFF_M01  16640    // ZT*64*4 = 4096  : {m0,m0,m10,m10} per (z,u)
#define OFF_M23  20736    // 4096            : {m11,m11,m12,m12}
#define SMEM_FLOATS 24832
#define SMEM_BYTES  (SMEM_FLOATS * 4)

__global__ void __launch_bounds__(THREADS, 2)
tp_kernel(const float* __restrict__ x, const float* __restrict__ y,
          const float* __restrict__ tpw, const float* __restrict__ w0,
          const float* __restrict__ w1, float* __restrict__ out)
{
    extern __shared__ float sm[];
    const int tid = threadIdx.x;

    // ---- prologue: stage weights (scaled) + premultiplied tp weights ----
    for (int i = tid; i < 8192; i += THREADS) {
        sm[OFF_W0 + i] = w0[i] * 0.125f;
        sm[OFF_W1 + i] = w1[i] * 0.125f;
    }
    if (tid < 64) {
        sm[OFF_TPW + tid]       = 0.7071067811865476f * tpw[tid];        // ca = C000*wA
        sm[OFF_TPW + 64 + tid]  = 0.7071067811865476f * tpw[64 + tid];   // cb = C011*wB
        sm[OFF_TPW + 128 + tid] = 0.7071067811865476f * tpw[128 + tid];  // cc = C101*wC
        sm[OFF_TPW + 192 + tid] = 0.4082482904638631f * tpw[192 + tid];  // cd = C110*wD
    }
    __syncthreads();

    const int warp = tid >> 5;
    const int lane = tid & 31;
    const unsigned sbase = (unsigned)__cvta_generic_to_shared(sm);
    const unsigned a_w0  = sbase + (OFF_W0 * 4) + lane * 16;   // + u*512
    const unsigned a_w1  = sbase + (OFF_W1 * 4) + lane * 16;
    const unsigned a_m01 = sbase + (OFF_M01 * 4);
    const unsigned a_m23 = sbase + (OFF_M23 * 4);

    const int ntiles = ZTOT / ZT;
    for (int tile = blockIdx.x; tile < ntiles; tile += gridDim.x) {
        const int z0 = tile * ZT;

        // ---- Phase A: compute mids for 16 z into smem (duplicated pairs) ----
        #pragma unroll
        for (int j = 0; j < 4; ++j) {
            const int zl = warp * 4 + j;
            const int zg = z0 + zl;
            const float4 yy = *(const float4*)(y + (size_t)zg * 4);
            const float* xr = x + (size_t)zg * 256;
            #pragma unroll
            for (int i = 0; i < 2; ++i) {
                const int u = lane + 32 * i;
                const float x0u = xr[u];
                const float a = xr[64 + 3 * u];
                const float b = xr[65 + 3 * u];
                const float c = xr[66 + 3 * u];
                const float ca = sm[OFF_TPW + u];
                const float cb = sm[OFF_TPW + 64 + u];
                const float cc = sm[OFF_TPW + 128 + u];
                const float cd = sm[OFF_TPW + 192 + u];
                const float d  = fmaf(a, yy.y, fmaf(b, yy.z, c * yy.w));
                const float m0 = fmaf(ca * x0u, yy.x, cd * d);
                const float q  = cb * x0u;
                const float r  = cc * yy.x;
                const float m10 = fmaf(q, yy.y, r * a);
                const float m11 = fmaf(q, yy.z, r * b);
                const float m12 = fmaf(q, yy.w, r * c);
                const int idx = zl * 64 + u;
                *(float4*)(sm + OFF_M01 + idx * 4) = make_float4(m0, m0, m10, m10);
                *(float4*)(sm + OFF_M23 + idx * 4) = make_float4(m11, m11, m12, m12);
            }
        }
        __syncthreads();

        // ---- Phase B: packed-f32x2 GEMM, warp = 4 z x 128 cols (4 cols/lane) ----
        {
            unsigned long long acc[4][8];
            #pragma unroll
            for (int zi = 0; zi < 4; ++zi)
                #pragma unroll
                for (int p = 0; p < 8; ++p) acc[zi][p] = 0ULL;

            const int zb = warp * 4;
            #pragma unroll 4
            for (int u = 0; u < 64; ++u) {
                unsigned long long w0a, w0b, w1a, w1b;
                lds_v2u64(a_w0 + u * 512, w0a, w0b);   // cols (4t,4t+1),(4t+2,4t+3)
                lds_v2u64(a_w1 + u * 512, w1a, w1b);
                #pragma unroll
                for (int zi = 0; zi < 4; ++zi) {
                    const unsigned moff = (unsigned)(((zb + zi) * 64 + u) * 16);
                    unsigned long long mm0, mm1, mm2, mm3;
                    lds_v2u64(a_m01 + moff, mm0, mm1);  // (m0,m0),(m10,m10)
                    lds_v2u64(a_m23 + moff, mm2, mm3);  // (m11,m11),(m12,m12)
                    acc[zi][0] = ffma2(mm0, w0a, acc[zi][0]);
                    acc[zi][1] = ffma2(mm0, w0b, acc[zi][1]);
                    acc[zi][2] = ffma2(mm1, w1a, acc[zi][2]);
                    acc[zi][3] = ffma2(mm1, w1b, acc[zi][3]);
                    acc[zi][4] = ffma2(mm2, w1a, acc[zi][4]);
                    acc[zi][5] = ffma2(mm2, w1b, acc[zi][5]);
                    acc[zi][6] = ffma2(mm3, w1a, acc[zi][6]);
                    acc[zi][7] = ffma2(mm3, w1b, acc[zi][7]);
                }
            }

            // ---- epilogue: unpack + coalesced v4 stores ----
            #pragma unroll
            for (int zi = 0; zi < 4; ++zi) {
                const int zg = z0 + zb + zi;
                const float2 a0 = unpack2(acc[zi][0]);
                const float2 a1 = unpack2(acc[zi][1]);
                const float2 a2 = unpack2(acc[zi][2]);
                const float2 a3 = unpack2(acc[zi][3]);
                const float2 a4 = unpack2(acc[zi][4]);
                const float2 a5 = unpack2(acc[zi][5]);
                const float2 a6 = unpack2(acc[zi][6]);
                const float2 a7 = unpack2(acc[zi][7]);
                float* o = out + (size_t)zg * 512;
                // out0 cols 4t..4t+3
                *(float4*)(o + 4 * lane) = make_float4(a0.x, a0.y, a1.x, a1.y);
                // out1: 12 consecutive floats at 128 + 12t  (w-major, k inner)
                float* o1 = o + 128 + 12 * lane;
                *(float4*)(o1)     = make_float4(a2.x, a4.x, a6.x, a2.y);
                *(float4*)(o1 + 4) = make_float4(a4.y, a6.y, a3.x, a5.x);
                *(float4*)(o1 + 8) = make_float4(a7.x, a3.y, a5.y, a7.y);
            }
        }
        __syncthreads();  // protect mid buffers before next tile's Phase A
    }
}

extern "C" void kernel_launch(void* const* d_in, const int* in_sizes, int n_in,
                              void* d_out, int out_size) {
    const float* x   = (const float*)d_in[0];
    const float* y   = (const float*)d_in[1];
    const float* tpw = (const float*)d_in[2];
    const float* w0  = (const float*)d_in[3];
    const float* w1  = (const float*)d_in[4];
    float* out = (float*)d_out;
    cudaFuncSetAttribute(tp_kernel, cudaFuncAttributeMaxDynamicSharedMemorySize,
                         SMEM_BYTES);
    tp_kernel<<<296, THREADS, SMEM_BYTES>>>(x, y, tpw, w0, w1, out);
}

// round 4
// speedup vs baseline: 1.3983x; 1.3983x over previous
#include <cuda_runtime.h>
#include <cstdint>

#define ZTOT    262144
#define THREADS 512
#define TILE_Z  128
#define NTILES  (ZTOT / TILE_Z)   // 2048
#define GRID    148

// ---- smem layout (bytes) ----
#define OFF_TPW   0                    // 256 floats = 1KB
#define OFF_A     1024                 // 4 channels x 32KB A-fragment arrays
#define A_CH      32768
#define OFF_STAGE (OFF_A + 4 * A_CH)   // 16 rows x 516 floats
#define PITCHF    516                  // floats per staged row (odd-ish pitch, 16B aligned)
#define SMEM_BYTES (OFF_STAGE + 16 * PITCHF * 4)   // 165120

__device__ __forceinline__ uint32_t to_tf32(float f) {
    uint32_t u;
    asm("cvt.rna.tf32.f32 %0, %1;" : "=r"(u) : "f"(f));
    return u;
}

__device__ __forceinline__ void mma8(float* c, uint4 a, uint32_t b0, uint32_t b1) {
    asm("mma.sync.aligned.m16n8k8.row.col.f32.tf32.tf32.f32 "
        "{%0,%1,%2,%3}, {%4,%5,%6,%7}, {%8,%9}, {%0,%1,%2,%3};"
        : "+f"(c[0]), "+f"(c[1]), "+f"(c[2]), "+f"(c[3])
        : "r"(a.x), "r"(a.y), "r"(a.z), "r"(a.w), "r"(b0), "r"(b1));
}

__global__ void __launch_bounds__(THREADS, 1)
tp_kernel(const float* __restrict__ x, const float* __restrict__ y,
          const float* __restrict__ tpw, const float* __restrict__ w0,
          const float* __restrict__ w1, float* __restrict__ out)
{
    extern __shared__ char smc[];
    float* smf = (float*)smc;
    const int tid  = threadIdx.x;
    const int warp = tid >> 5;
    const int lane = tid & 31;
    const int g    = lane >> 2;      // groupID
    const int th4  = lane & 3;       // thread-in-group

    // ---- prologue 1: B fragments in registers (weights x0.125, tf32) ----
    // warp -> (channel ch, n-quarter q). ch0 uses w0; ch1..3 use w1.
    const int ch = warp >> 2;
    const int q  = warp & 3;
    const float* W = (ch == 0) ? w0 : w1;
    uint32_t bfr[8][4][2];
    #pragma unroll
    for (int ki = 0; ki < 8; ++ki)
        #pragma unroll
        for (int ni = 0; ni < 4; ++ni) {
            const int n  = q * 32 + ni * 8 + g;
            const int u0 = ki * 8 + th4;
            bfr[ki][ni][0] = to_tf32(W[u0 * 128 + n] * 0.125f);
            bfr[ki][ni][1] = to_tf32(W[(u0 + 4) * 128 + n] * 0.125f);
        }

    // ---- prologue 2: tp_w with C-consts folded ----
    if (tid < 64) {
        smf[OFF_TPW/4 + tid]       = 0.7071067811865476f * tpw[tid];        // ca
        smf[OFF_TPW/4 + 64 + tid]  = 0.7071067811865476f * tpw[64 + tid];   // cb
        smf[OFF_TPW/4 + 128 + tid] = 0.7071067811865476f * tpw[128 + tid];  // cc
        smf[OFF_TPW/4 + 192 + tid] = 0.4082482904638631f * tpw[192 + tid];  // cd
    }
    __syncthreads();

    // Phase-A fixed per-thread indices: thread -> (z' = tid>>2, u-group = tid&3)
    const int zA  = tid >> 2;
    const int ug  = tid & 3;
    const int miA = zA >> 4;
    const int i1A = (zA >> 3) & 1;
    const int gA  = zA & 7;

    // Phase-B A-fragment base: float idx = ch*8192 + (mi*8+ki)*128 + lane*4
    float* aArr = smf + OFF_A/4 + ch * (A_CH/4) + lane * 4;
    float* stg  = smf + OFF_STAGE/4;

    for (int tile = blockIdx.x; tile < NTILES; tile += GRID) {
        const int z0 = tile * TILE_Z;

        // ================= Phase A: mids -> A-fragment-ordered smem =============
        {
            const int zg = z0 + zA;
            const float4 yy = *(const float4*)(y + (size_t)zg * 4);
            const float* xr = x + (size_t)zg * 256;
            #pragma unroll
            for (int h = 0; h < 2; ++h) {
                float x0b[8], x1b[24];
                #pragma unroll
                for (int t = 0; t < 2; ++t)
                    *(float4*)(x0b + 4*t) = *(const float4*)(xr + ug*16 + h*8 + 4*t);
                #pragma unroll
                for (int t = 0; t < 6; ++t)
                    *(float4*)(x1b + 4*t) = *(const float4*)(xr + 64 + ug*48 + h*24 + 4*t);
                #pragma unroll
                for (int j = 0; j < 8; ++j) {
                    const int u = ug * 16 + h * 8 + j;
                    const float x0u = x0b[j];
                    const float a = x1b[3*j], b = x1b[3*j+1], c = x1b[3*j+2];
                    const float ca = smf[OFF_TPW/4 + u];
                    const float cb = smf[OFF_TPW/4 + 64 + u];
                    const float cc = smf[OFF_TPW/4 + 128 + u];
                    const float cd = smf[OFF_TPW/4 + 192 + u];
                    const float d  = fmaf(a, yy.y, fmaf(b, yy.z, c * yy.w));
                    const float m0 = fmaf(ca * x0u, yy.x, cd * d);
                    const float qq = cb * x0u;
                    const float rr = cc * yy.x;
                    // A-fragment address for element (z', u)
                    const int ki = u >> 3;
                    const int i2 = (u >> 2) & 1;
                    const int l4 = gA * 4 + (u & 3);
                    const int fidx = OFF_A/4 + (miA*8 + ki)*128 + l4*4 + (i1A + 2*i2);
                    ((uint32_t*)smf)[fidx]            = to_tf32(m0);
                    ((uint32_t*)smf)[fidx + 8192]     = to_tf32(fmaf(qq, yy.y, rr * a));
                    ((uint32_t*)smf)[fidx + 16384]    = to_tf32(fmaf(qq, yy.z, rr * b));
                    ((uint32_t*)smf)[fidx + 24576]    = to_tf32(fmaf(qq, yy.w, rr * c));
                }
            }
        }
        __syncthreads();

        // ================= Phase B: warp MMA + staged coalesced epilogue ========
        #pragma unroll 1
        for (int mi = 0; mi < 8; ++mi) {
            float acc[4][4];
            #pragma unroll
            for (int ni = 0; ni < 4; ++ni)
                #pragma unroll
                for (int p = 0; p < 4; ++p) acc[ni][p] = 0.f;

            #pragma unroll
            for (int ki = 0; ki < 8; ++ki) {
                const uint4 av = *(const uint4*)(aArr + (mi*8 + ki)*128);
                #pragma unroll
                for (int ni = 0; ni < 4; ++ni)
                    mma8(acc[ni], av, bfr[ki][ni][0], bfr[ki][ni][1]);
            }

            // stage this 16-row stripe (rows z0+16mi .. +15), final column layout
            #pragma unroll
            for (int ni = 0; ni < 4; ++ni) {
                const int nc = q * 32 + ni * 8 + 2 * th4;
                if (ch == 0) {
                    *(float2*)(stg + g * PITCHF + nc)       = make_float2(acc[ni][0], acc[ni][1]);
                    *(float2*)(stg + (g + 8) * PITCHF + nc) = make_float2(acc[ni][2], acc[ni][3]);
                } else {
                    const int c0 = 128 + 3 * nc + (ch - 1);
                    stg[g * PITCHF + c0]           = acc[ni][0];
                    stg[g * PITCHF + c0 + 3]       = acc[ni][1];
                    stg[(g + 8) * PITCHF + c0]     = acc[ni][2];
                    stg[(g + 8) * PITCHF + c0 + 3] = acc[ni][3];
                }
            }
            __syncthreads();

            // coalesced copy: 16 rows x 512 floats
            {
                const uint4* st4 = (const uint4*)stg;
                float* ob = out + (size_t)(z0 + 16 * mi) * 512;
                #pragma unroll
                for (int it = 0; it < 4; ++it) {
                    const int idx = tid + it * THREADS;        // 0..2047
                    const int z16 = idx >> 7, f = idx & 127;
                    *(uint4*)(ob + (size_t)z16 * 512 + f * 4) = st4[z16 * (PITCHF/4) + f];
                }
            }
            __syncthreads();
        }
        // last __syncthreads also protects A arrays before next tile's Phase A
    }
}

extern "C" void kernel_launch(void* const* d_in, const int* in_sizes, int n_in,
                              void* d_out, int out_size) {
    const float* x   = (const float*)d_in[0];
    const float* y   = (const float*)d_in[1];
    const float* tpw = (const float*)d_in[2];
    const float* w0  = (const float*)d_in[3];
    const float* w1  = (const float*)d_in[4];
    float* out = (float*)d_out;
    cudaFuncSetAttribute(tp_kernel, cudaFuncAttributeMaxDynamicSharedMemorySize,
                         SMEM_BYTES);
    tp_kernel<<<GRID, THREADS, SMEM_BYTES>>>(x, y, tpw, w0, w1, out);
}

// round 6
// speedup vs baseline: 2.3535x; 1.6831x over previous
#include <cuda_runtime.h>
#include <cstdint>

#define ZTOT    262144
#define THREADS 512
#define TILE_Z  128
#define NTILES  (ZTOT / TILE_Z)   // 2048
#define GRID    148

// ---- smem layout (bytes) ----
// A frags: 4 ch x 16KB (32 blocks x 512B per ch, for 64 z)
#define OFF_A    0
#define A_CHB    16384
// x stage: 2 buffers x (64 rows x 260 floats x 4B = 66560)
#define XPITCHB  1040
#define OFF_X0   65536
#define OFF_X1   (OFF_X0 + 66560)          // 132096
#define OFF_Y    (OFF_X1 + 66560)          // 198656 ; 2 x 64 float4
#define OFF_TPW  (OFF_Y + 2048)            // 200704 ; 256 floats
#define SMEM_BYTES (OFF_TPW + 1024)        // 201728
#define PITCHF   516                       // epilogue stage pitch (floats)

__device__ __forceinline__ uint32_t to_tf32(float f) {
    uint32_t u;
    asm("cvt.rna.tf32.f32 %0, %1;" : "=r"(u) : "f"(f));
    return u;
}

__device__ __forceinline__ void mma8(float* c, uint4 a, uint32_t b0, uint32_t b1) {
    asm("mma.sync.aligned.m16n8k8.row.col.f32.tf32.tf32.f32 "
        "{%0,%1,%2,%3}, {%4,%5,%6,%7}, {%8,%9}, {%0,%1,%2,%3};"
        : "+f"(c[0]), "+f"(c[1]), "+f"(c[2]), "+f"(c[3])
        : "r"(a.x), "r"(a.y), "r"(a.z), "r"(a.w), "r"(b0), "r"(b1));
}

__device__ __forceinline__ void cpasync16(uint32_t dst, const void* src) {
    asm volatile("cp.async.cg.shared.global [%0], [%1], 16;" :: "r"(dst), "l"(src));
}
#define CP_COMMIT() asm volatile("cp.async.commit_group;" ::: "memory")
#define CP_WAIT(n)  asm volatile("cp.async.wait_group %0;" :: "n"(n) : "memory")

__global__ void __launch_bounds__(THREADS, 1)
tp_kernel(const float* __restrict__ x, const float* __restrict__ y,
          const float* __restrict__ tpw, const float* __restrict__ w0,
          const float* __restrict__ w1, float* __restrict__ out)
{
    extern __shared__ char smc[];
    float* smf = (float*)smc;
    const int tid  = threadIdx.x;
    const int warp = tid >> 5;
    const int lane = tid & 31;
    const int g    = lane >> 2;
    const int th4  = lane & 3;
    const uint32_t sb = (uint32_t)__cvta_generic_to_shared(smc);

    // ---- Phase-B roles + B fragments in registers (x0.125, tf32) ----
    const int ch = warp >> 2;
    const int q  = warp & 3;
    const float* W = (ch == 0) ? w0 : w1;
    uint32_t bfr[8][4][2];
    #pragma unroll
    for (int ki = 0; ki < 8; ++ki)
        #pragma unroll
        for (int ni = 0; ni < 4; ++ni) {
            const int n  = q * 32 + ni * 8 + g;
            const int u0 = ki * 8 + th4;
            bfr[ki][ni][0] = to_tf32(W[u0 * 128 + n] * 0.125f);
            bfr[ki][ni][1] = to_tf32(W[(u0 + 4) * 128 + n] * 0.125f);
        }

    if (tid < 64) {
        smf[OFF_TPW/4 + tid]       = 0.7071067811865476f * tpw[tid];        // ca
        smf[OFF_TPW/4 + 64 + tid]  = 0.7071067811865476f * tpw[64 + tid];   // cb
        smf[OFF_TPW/4 + 128 + tid] = 0.7071067811865476f * tpw[128 + tid];  // cc
        smf[OFF_TPW/4 + 192 + tid] = 0.4082482904638631f * tpw[192 + tid];  // cd
    }

    // ---- Phase-A roles (64-z half) ----
    const int miL = warp >> 2;        // 0..3
    const int kb  = (warp & 3) * 2;   // ki = kb, kb+1
    const int r0  = miL * 16 + g;     // row (i1=0) within the 64-row half

    float* aArr = smf + OFF_A/4 + ch * (A_CHB/4) + lane * 4;   // Phase-B A base

    // helper: stage one 64-z half (x + y) into buffer b   [8+? cp.async/thread]
    auto load_half = [&](int t, int h, int b) {
        const float* xsrc = x + ((size_t)t * TILE_Z + h * 64) * 256;
        const uint32_t xb = sb + ((b == 0) ? OFF_X0 : OFF_X1);
        #pragma unroll
        for (int it = 0; it < 8; ++it) {
            const int idx = tid + it * THREADS;     // 0..4095
            const int row = idx >> 6, c = idx & 63;
            cpasync16(xb + row * XPITCHB + c * 16, xsrc + row * 256 + c * 4);
        }
        if (tid < 64)
            cpasync16(sb + OFF_Y + b * 1024 + tid * 16,
                      y + ((size_t)t * TILE_Z + h * 64 + tid) * 4);
        CP_COMMIT();
    };

    int tile = blockIdx.x;
    int buf = 0;
    if (tile < NTILES) load_half(tile, 0, 0);
    __syncthreads();   // also covers tpw stores

    for (; tile < NTILES; tile += GRID) {
        #pragma unroll 1
        for (int h = 0; h < 2; ++h) {
            // prefetch next half
            int nt = tile, nh = h + 1;
            if (nh == 2) { nt = tile + GRID; nh = 0; }
            const bool has_next = (nt < NTILES);
            if (has_next) load_half(nt, nh, buf ^ 1);
            if (has_next) { CP_WAIT(1); } else { CP_WAIT(0); }
            __syncthreads();

            const float* xs = smf + ((buf == 0) ? OFF_X0 : OFF_X1) / 4;
            const float4* ys = (const float4*)(smc + OFF_Y) + buf * 64;
            float* stg = smf + ((buf == 0) ? OFF_X0 : OFF_X1) / 4;  // reuse after Phase A

            // ---- Phase A: mids -> A fragments, conflict-free ----
            {
                const float4 yy0 = ys[r0];
                const float4 yy1 = ys[r0 + 8];
                #pragma unroll
                for (int kk = 0; kk < 2; ++kk) {
                    const int ki = kb + kk;
                    const int u  = ki * 8 + th4;
                    const float caA = smf[OFF_TPW/4 + u],       caB = smf[OFF_TPW/4 + u + 4];
                    const float cbA = smf[OFF_TPW/4 + 64 + u],  cbB = smf[OFF_TPW/4 + 68 + u];
                    const float ccA = smf[OFF_TPW/4 + 128 + u], ccB = smf[OFF_TPW/4 + 132 + u];
                    const float cdA = smf[OFF_TPW/4 + 192 + u], cdB = smf[OFF_TPW/4 + 196 + u];
                    uint4 q0, q1, q2, q3;
                    #pragma unroll
                    for (int i1 = 0; i1 < 2; ++i1) {
                        const float4 yy = i1 ? yy1 : yy0;
                        const float* xr = xs + (r0 + 8 * i1) * (XPITCHB/4);
                        const float x0A = xr[u], x0B = xr[u + 4];
                        const float aA = xr[64 + 3*u], bA = xr[65 + 3*u], cA = xr[66 + 3*u];
                        const float aB = xr[76 + 3*u], bB = xr[77 + 3*u], cB = xr[78 + 3*u];
                        const float dA  = fmaf(aA, yy.y, fmaf(bA, yy.z, cA * yy.w));
                        const float m0A = fmaf(caA * x0A, yy.x, cdA * dA);
                        const float qqA = cbA * x0A, rrA = ccA * yy.x;
                        const float dB  = fmaf(aB, yy.y, fmaf(bB, yy.z, cB * yy.w));
                        const float m0B = fmaf(caB * x0B, yy.x, cdB * dB);
                        const float qqB = cbB * x0B, rrB = ccB * yy.x;
                        const uint32_t v0A = to_tf32(m0A);
                        const uint32_t v1A = to_tf32(fmaf(qqA, yy.y, rrA * aA));
                        const uint32_t v2A = to_tf32(fmaf(qqA, yy.z, rrA * bA));
                        const uint32_t v3A = to_tf32(fmaf(qqA, yy.w, rrA * cA));
                        const uint32_t v0B = to_tf32(m0B);
                        const uint32_t v1B = to_tf32(fmaf(qqB, yy.y, rrB * aB));
                        const uint32_t v2B = to_tf32(fmaf(qqB, yy.z, rrB * bB));
                        const uint32_t v3B = to_tf32(fmaf(qqB, yy.w, rrB * cB));
                        if (i1 == 0) {
                            q0.x = v0A; q0.z = v0B;  q1.x = v1A; q1.z = v1B;
                            q2.x = v2A; q2.z = v2B;  q3.x = v3A; q3.z = v3B;
                        } else {
                            q0.y = v0A; q0.w = v0B;  q1.y = v1A; q1.w = v1B;
                            q2.y = v2A; q2.w = v2B;  q3.y = v3A; q3.w = v3B;
                        }
                    }
                    const int block = miL * 8 + ki;   // 0..31
                    char* ab = smc + OFF_A + block * 512 + lane * 16;
                    *(uint4*)(ab)               = q0;
                    *(uint4*)(ab + A_CHB)       = q1;
                    *(uint4*)(ab + 2 * A_CHB)   = q2;
                    *(uint4*)(ab + 3 * A_CHB)   = q3;
                }
            }
            __syncthreads();

            // ---- Phase B: MMA + staged coalesced epilogue ----
            #pragma unroll 1
            for (int mi = 0; mi < 4; ++mi) {
                float acc[4][4];
                #pragma unroll
                for (int ni = 0; ni < 4; ++ni)
                    #pragma unroll
                    for (int p = 0; p < 4; ++p) acc[ni][p] = 0.f;

                #pragma unroll
                for (int ki = 0; ki < 8; ++ki) {
                    const uint4 av = *(const uint4*)(aArr + (mi * 8 + ki) * 128);
                    #pragma unroll
                    for (int ni = 0; ni < 4; ++ni)
                        mma8(acc[ni], av, bfr[ki][ni][0], bfr[ki][ni][1]);
                }

                #pragma unroll
                for (int ni = 0; ni < 4; ++ni) {
                    const int nc = q * 32 + ni * 8 + 2 * th4;
                    if (ch == 0) {
                        *(float2*)(stg + g * PITCHF + nc)       = make_float2(acc[ni][0], acc[ni][1]);
                        *(float2*)(stg + (g + 8) * PITCHF + nc) = make_float2(acc[ni][2], acc[ni][3]);
                    } else {
                        const int c0 = 128 + 3 * nc + (ch - 1);
                        stg[g * PITCHF + c0]           = acc[ni][0];
                        stg[g * PITCHF + c0 + 3]       = acc[ni][1];
                        stg[(g + 8) * PITCHF + c0]     = acc[ni][2];
                        stg[(g + 8) * PITCHF + c0 + 3] = acc[ni][3];
                    }
                }
                __syncthreads();

                {
                    const uint4* st4 = (const uint4*)stg;
                    float* ob = out + ((size_t)tile * TILE_Z + h * 64 + 16 * mi) * 512;
                    #pragma unroll
                    for (int it = 0; it < 4; ++it) {
                        const int idx = tid + it * THREADS;     // 0..2047
                        const int z16 = idx >> 7, f = idx & 127;
                        *(uint4*)(ob + (size_t)z16 * 512 + f * 4) = st4[z16 * (PITCHF/4) + f];
                    }
                }
                __syncthreads();
            }
            buf ^= 1;
        }
    }
}

extern "C" void kernel_launch(void* const* d_in, const int* in_sizes, int n_in,
                              void* d_out, int out_size) {
    const float* x   = (const float*)d_in[0];
    const float* y   = (const float*)d_in[1];
    const float* tpw = (const float*)d_in[2];
    const float* w0  = (const float*)d_in[3];
    const float* w1  = (const float*)d_in[4];
    float* out = (float*)d_out;
    cudaFuncSetAttribute(tp_kernel, cudaFuncAttributeMaxDynamicSharedMemorySize,
                         SMEM_BYTES);
    tp_kernel<<<GRID, THREADS, SMEM_BYTES>>>(x, y, tpw, w0, w1, out);
}

// round 10
// speedup vs baseline: 2.5246x; 1.0727x over previous
#include <cuda_runtime.h>
#include <cstdint>

#define ZTOT    262144
#define THREADS 512
#define TILE_Z  128
#define NTILES  (ZTOT / TILE_Z)   // 2048
#define GRID    148

// ---- smem layout (bytes) ----
#define OFF_A    0
#define A_CHB    16384                     // per-channel A frags (64 z)
#define XPITCHB  1040                      // x stage row pitch (260 floats)
#define OFF_X0   65536
#define OFF_X1   (OFF_X0 + 66560)          // 132096
#define OFF_Y    (OFF_X1 + 66560)          // 198656
#define OFF_TPW  (OFF_Y + 2048)            // 200704
#define SMEM_BYTES (OFF_TPW + 1024)        // 201728
#define PITCHF   388                       // epilogue stage pitch (floats), 97 uint4

__device__ __forceinline__ uint32_t to_tf32(float f) {
    uint32_t u;
    asm("cvt.rna.tf32.f32 %0, %1;" : "=r"(u) : "f"(f));
    return u;
}

__device__ __forceinline__ void mma8(float* c, uint4 a, uint32_t b0, uint32_t b1) {
    asm("mma.sync.aligned.m16n8k8.row.col.f32.tf32.tf32.f32 "
        "{%0,%1,%2,%3}, {%4,%5,%6,%7}, {%8,%9}, {%0,%1,%2,%3};"
        : "+f"(c[0]), "+f"(c[1]), "+f"(c[2]), "+f"(c[3])
        : "r"(a.x), "r"(a.y), "r"(a.z), "r"(a.w), "r"(b0), "r"(b1));
}

__device__ __forceinline__ void cpasync16(uint32_t dst, const void* src) {
    asm volatile("cp.async.cg.shared.global [%0], [%1], 16;" :: "r"(dst), "l"(src));
}
#define CP_COMMIT() asm volatile("cp.async.commit_group;" ::: "memory")
#define CP_WAIT(n)  asm volatile("cp.async.wait_group %0;" :: "n"(n) : "memory")

__global__ void __launch_bounds__(THREADS, 1)
tp_kernel(const float* __restrict__ x, const float* __restrict__ y,
          const float* __restrict__ tpw, const float* __restrict__ w0,
          const float* __restrict__ w1, float* __restrict__ out)
{
    extern __shared__ char smc[];
    float* smf = (float*)smc;
    const int tid  = threadIdx.x;
    const int warp = tid >> 5;
    const int lane = tid & 31;
    const int g    = lane >> 2;
    const int th4  = lane & 3;
    const uint32_t sb = (uint32_t)__cvta_generic_to_shared(smc);

    // ---- Phase-B roles + B fragments in registers (x0.125, tf32) ----
    const int ch = warp >> 2;
    const int q  = warp & 3;
    const float* W = (ch == 0) ? w0 : w1;
    uint32_t bfr[8][4][2];
    #pragma unroll
    for (int ki = 0; ki < 8; ++ki)
        #pragma unroll
        for (int ni = 0; ni < 4; ++ni) {
            const int n  = q * 32 + ni * 8 + g;
            const int u0 = ki * 8 + th4;
            bfr[ki][ni][0] = to_tf32(W[u0 * 128 + n] * 0.125f);
            bfr[ki][ni][1] = to_tf32(W[(u0 + 4) * 128 + n] * 0.125f);
        }

    if (tid < 64) {
        smf[OFF_TPW/4 + tid]       = 0.7071067811865476f * tpw[tid];        // ca
        smf[OFF_TPW/4 + 64 + tid]  = 0.7071067811865476f * tpw[64 + tid];   // cb
        smf[OFF_TPW/4 + 128 + tid] = 0.7071067811865476f * tpw[128 + tid];  // cc
        smf[OFF_TPW/4 + 192 + tid] = 0.4082482904638631f * tpw[192 + tid];  // cd
    }

    // ---- Phase-A roles (64-z half) ----
    const int miL = warp >> 2;        // 0..3
    const int kb  = (warp & 3) * 2;   // ki = kb, kb+1
    const int r0  = miL * 16 + g;

    float* aArr = smf + OFF_A/4 + ch * (A_CHB/4) + lane * 4;

    auto load_half = [&](int t, int h, int b) {
        const float* xsrc = x + ((size_t)t * TILE_Z + h * 64) * 256;
        const uint32_t xb = sb + ((b == 0) ? OFF_X0 : OFF_X1);
        #pragma unroll
        for (int it = 0; it < 8; ++it) {
            const int idx = tid + it * THREADS;
            const int row = idx >> 6, c = idx & 63;
            cpasync16(xb + row * XPITCHB + c * 16, xsrc + row * 256 + c * 4);
        }
        if (tid < 64)
            cpasync16(sb + OFF_Y + b * 1024 + tid * 16,
                      y + ((size_t)t * TILE_Z + h * 64 + tid) * 4);
        CP_COMMIT();
    };

    int tile = blockIdx.x;
    int buf = 0;
    if (tile < NTILES) load_half(tile, 0, 0);
    __syncthreads();

    for (; tile < NTILES; tile += GRID) {
        #pragma unroll 1
        for (int h = 0; h < 2; ++h) {
            int nt = tile, nh = h + 1;
            if (nh == 2) { nt = tile + GRID; nh = 0; }
            const bool has_next = (nt < NTILES);
            if (has_next) load_half(nt, nh, buf ^ 1);
            if (has_next) { CP_WAIT(1); } else { CP_WAIT(0); }
            __syncthreads();

            const float* xs = smf + ((buf == 0) ? OFF_X0 : OFF_X1) / 4;
            const float4* ys = (const float4*)(smc + OFF_Y) + buf * 64;
            float* stg = smf + ((buf == 0) ? OFF_X0 : OFF_X1) / 4;  // reuse after A

            // ---- Phase A: mids -> A fragments, conflict-free ----
            {
                const float4 yy0 = ys[r0];
                const float4 yy1 = ys[r0 + 8];
                #pragma unroll
                for (int kk = 0; kk < 2; ++kk) {
                    const int ki = kb + kk;
                    const int u  = ki * 8 + th4;
                    const float caA = smf[OFF_TPW/4 + u],       caB = smf[OFF_TPW/4 + u + 4];
                    const float cbA = smf[OFF_TPW/4 + 64 + u],  cbB = smf[OFF_TPW/4 + 68 + u];
                    const float ccA = smf[OFF_TPW/4 + 128 + u], ccB = smf[OFF_TPW/4 + 132 + u];
                    const float cdA = smf[OFF_TPW/4 + 192 + u], cdB = smf[OFF_TPW/4 + 196 + u];
                    uint4 q0, q1, q2, q3;
                    #pragma unroll
                    for (int i1 = 0; i1 < 2; ++i1) {
                        const float4 yy = i1 ? yy1 : yy0;
                        const float* xr = xs + (r0 + 8 * i1) * (XPITCHB/4);
                        const float x0A = xr[u], x0B = xr[u + 4];
                        const float aA = xr[64 + 3*u], bA = xr[65 + 3*u], cA = xr[66 + 3*u];
                        const float aB = xr[76 + 3*u], bB = xr[77 + 3*u], cB = xr[78 + 3*u];
                        const float dA  = fmaf(aA, yy.y, fmaf(bA, yy.z, cA * yy.w));
                        const float m0A = fmaf(caA * x0A, yy.x, cdA * dA);
                        const float qqA = cbA * x0A, rrA = ccA * yy.x;
                        const float dB  = fmaf(aB, yy.y, fmaf(bB, yy.z, cB * yy.w));
                        const float m0B = fmaf(caB * x0B, yy.x, cdB * dB);
                        const float qqB = cbB * x0B, rrB = ccB * yy.x;
                        const uint32_t v0A = to_tf32(m0A);
                        const uint32_t v1A = to_tf32(fmaf(qqA, yy.y, rrA * aA));
                        const uint32_t v2A = to_tf32(fmaf(qqA, yy.z, rrA * bA));
                        const uint32_t v3A = to_tf32(fmaf(qqA, yy.w, rrA * cA));
                        const uint32_t v0B = to_tf32(m0B);
                        const uint32_t v1B = to_tf32(fmaf(qqB, yy.y, rrB * aB));
                        const uint32_t v2B = to_tf32(fmaf(qqB, yy.z, rrB * bB));
                        const uint32_t v3B = to_tf32(fmaf(qqB, yy.w, rrB * cB));
                        if (i1 == 0) {
                            q0.x = v0A; q0.z = v0B;  q1.x = v1A; q1.z = v1B;
                            q2.x = v2A; q2.z = v2B;  q3.x = v3A; q3.z = v3B;
                        } else {
                            q0.y = v0A; q0.w = v0B;  q1.y = v1A; q1.w = v1B;
                            q2.y = v2A; q2.w = v2B;  q3.y = v3A; q3.w = v3B;
                        }
                    }
                    const int block = miL * 8 + ki;
                    char* ab = smc + OFF_A + block * 512 + lane * 16;
                    *(uint4*)(ab)               = q0;
                    *(uint4*)(ab + A_CHB)       = q1;
                    *(uint4*)(ab + 2 * A_CHB)   = q2;
                    *(uint4*)(ab + 3 * A_CHB)   = q3;
                }
            }
            __syncthreads();

            // ---- Phase B: 2 passes of (2 mi MMA) + 32-row staged epilogue ----
            const size_t zb = (size_t)tile * TILE_Z + h * 64;
            #pragma unroll 1
            for (int p = 0; p < 2; ++p) {
                #pragma unroll
                for (int mm = 0; mm < 2; ++mm) {
                    const int mi = 2 * p + mm;
                    float acc[4][4];
                    #pragma unroll
                    for (int ni = 0; ni < 4; ++ni)
                        #pragma unroll
                        for (int pp = 0; pp < 4; ++pp) acc[ni][pp] = 0.f;

                    #pragma unroll
                    for (int ki = 0; ki < 8; ++ki) {
                        const uint4 av = *(const uint4*)(aArr + (mi * 8 + ki) * 128);
                        #pragma unroll
                        for (int ni = 0; ni < 4; ++ni)
                            mma8(acc[ni], av, bfr[ki][ni][0], bfr[ki][ni][1]);
                    }

                    if (ch == 0) {
                        // direct sector-aligned STG.64 into out[:,0:128]
                        float* ob = out + (zb + 16 * mi) * 512;
                        #pragma unroll
                        for (int ni = 0; ni < 4; ++ni) {
                            const int nc = q * 32 + ni * 8 + 2 * th4;
                            *(float2*)(ob + (size_t)g * 512 + nc) =
                                make_float2(acc[ni][0], acc[ni][1]);
                            *(float2*)(ob + (size_t)(g + 8) * 512 + nc) =
                                make_float2(acc[ni][2], acc[ni][3]);
                        }
                    } else {
                        float* sr = stg + (16 * mm) * PITCHF;
                        #pragma unroll
                        for (int ni = 0; ni < 4; ++ni) {
                            const int c0 = 3 * (q * 32 + ni * 8 + 2 * th4) + (ch - 1);
                            sr[g * PITCHF + c0]           = acc[ni][0];
                            sr[g * PITCHF + c0 + 3]       = acc[ni][1];
                            sr[(g + 8) * PITCHF + c0]     = acc[ni][2];
                            sr[(g + 8) * PITCHF + c0 + 3] = acc[ni][3];
                        }
                    }
                }
                __syncthreads();

                // copy 32 rows x 384 floats -> out[:,128:512]
                {
                    const uint4* st4 = (const uint4*)stg;
                    float* ob = out + (zb + 32 * p) * 512 + 128;
                    #pragma unroll
                    for (int it = 0; it < 6; ++it) {
                        const int idx = tid + it * THREADS;   // 0..3071
                        const int r = idx / 96, f = idx - r * 96;
                        *(uint4*)(ob + (size_t)r * 512 + f * 4) = st4[r * 97 + f];
                    }
                }
                __syncthreads();
            }
            buf ^= 1;
        }
    }
}

extern "C" void kernel_launch(void* const* d_in, const int* in_sizes, int n_in,
                              void* d_out, int out_size) {
    const float* x   = (const float*)d_in[0];
    const float* y   = (const float*)d_in[1];
    const float* tpw = (const float*)d_in[2];
    const float* w0  = (const float*)d_in[3];
    const float* w1  = (const float*)d_in[4];
    float* out = (float*)d_out;
    cudaFuncSetAttribute(tp_kernel, cudaFuncAttributeMaxDynamicSharedMemorySize,
                         SMEM_BYTES);
    tp_kernel<<<GRID, THREADS, SMEM_BYTES>>>(x, y, tpw, w0, w1, out);
}